// round 9
// baseline (speedup 1.0000x reference)
#include <cuda_runtime.h>
#include <cuda_bf16.h>
#include <math.h>

// ---------------------------------------------------------------------------
// 2-layer GCN via CSR-gather, forked-stream graph:
//   branch B (main): deg -> scan1 -> scan3 (inline block-offsets) -> fill
//   branch A (s2):   wsplit -> gemm1 (3xTF32 mma, double-buffered cp.async)
//   join -> gather1 (agg+relu+W2) -> gather2 (agg+log_softmax)
// g_degcnt starts zero (static init) and is re-zeroed by k_fill each call.
// edge_index arrives as int32.
// ---------------------------------------------------------------------------

#define F_IN 512
#define HID  16
#define NCLS 2
#define NMAX 131072
#define EMAX 3276800
#define SCAN_CH 2048

__device__ __align__(16) int   g_degcnt[NMAX];     // zero-init; k_fill re-zeros
__device__ __align__(16) int   g_incl[NMAX];
__device__ __align__(16) int   g_off[NMAX + 1];
__device__ __align__(16) int   g_cur[NMAX];
__device__ __align__(16) int   g_bsum[256];
__device__ __align__(16) float g_dinv[NMAX];
__device__ __align__(16) float g_h1[NMAX * HID];
__device__ __align__(16) float g_h2[NMAX * NCLS];
__device__ __align__(16) int2  g_epack[EMAX];      // {src, bits(dinv[src])}
__device__ __align__(16) float g_w1hi[F_IN * HID];
__device__ __align__(16) float g_w1lo[F_IN * HID];

// ---------------- helpers ----------------
__device__ __forceinline__ unsigned cvt_tf32(float f) {
    unsigned r; asm("cvt.rna.tf32.f32 %0, %1;" : "=r"(r) : "f"(f)); return r;
}
__device__ __forceinline__ void mma_tf32(float* d, const unsigned* a,
                                         unsigned b0, unsigned b1) {
    asm("mma.sync.aligned.m16n8k8.row.col.f32.tf32.tf32.f32 "
        "{%0,%1,%2,%3}, {%4,%5,%6,%7}, {%8,%9}, {%0,%1,%2,%3};"
        : "+f"(d[0]), "+f"(d[1]), "+f"(d[2]), "+f"(d[3])
        : "r"(a[0]), "r"(a[1]), "r"(a[2]), "r"(a[3]), "r"(b0), "r"(b1));
}
__device__ __forceinline__ void cp_async16(void* smem_dst, const void* gmem_src) {
    unsigned sm;
    asm("{ .reg .u64 t; cvta.to.shared.u64 t, %1; cvt.u32.u64 %0, t; }"
        : "=r"(sm) : "l"(smem_dst));
    asm volatile("cp.async.cg.shared.global [%0], [%1], 16;"
                 :: "r"(sm), "l"(gmem_src) : "memory");
}
__device__ __forceinline__ void cp_commit() {
    asm volatile("cp.async.commit_group;" ::: "memory");
}
template <int NW>
__device__ __forceinline__ void cp_wait() {
    asm volatile("cp.async.wait_group %0;" :: "n"(NW) : "memory");
}

// ---------------- degree count (4 edges / thread) ----------------
__global__ void k_deg(const int* __restrict__ dst, int E) {
    int i = blockIdx.x * blockDim.x + threadIdx.x;
    int base = i * 4;
    if (base + 3 < E) {
        int4 d = *(const int4*)(dst + base);
        atomicAdd(&g_degcnt[d.x], 1);
        atomicAdd(&g_degcnt[d.y], 1);
        atomicAdd(&g_degcnt[d.z], 1);
        atomicAdd(&g_degcnt[d.w], 1);
    } else {
        for (int e = base; e < E; e++) atomicAdd(&g_degcnt[dst[e]], 1);
    }
}

// ---------------- W1 split into tf32 hi/lo ----------------
__global__ void k_wsplit(const float* __restrict__ W1) {
    int i = blockIdx.x * blockDim.x + threadIdx.x;
    if (i >= F_IN * HID) return;
    float w = W1[i];
    unsigned hi = cvt_tf32(w);
    float hif = __uint_as_float(hi);
    g_w1hi[i] = hif;
    g_w1lo[i] = __uint_as_float(cvt_tf32(w - hif));
}

// ---------------- scan pass 1: per-block inclusive scan + block sums --------
__global__ __launch_bounds__(512) void k_scan1(int N) {
    __shared__ int wsum[16];
    const int t = threadIdx.x;
    const int base = blockIdx.x * SCAN_CH + t * 4;
    int v0 = (base + 0 < N) ? g_degcnt[base + 0] : 0;
    int v1 = (base + 1 < N) ? g_degcnt[base + 1] : 0;
    int v2 = (base + 2 < N) ? g_degcnt[base + 2] : 0;
    int v3 = (base + 3 < N) ? g_degcnt[base + 3] : 0;
    int s1 = v0 + v1, s2 = s1 + v2, s3 = s2 + v3;
    int tot = s3;

    int lane = t & 31, w = t >> 5;
    int sc = tot;
#pragma unroll
    for (int d = 1; d < 32; d <<= 1) {
        int u = __shfl_up_sync(0xffffffffu, sc, d);
        if (lane >= d) sc += u;
    }
    if (lane == 31) wsum[w] = sc;
    __syncthreads();
    if (w == 0) {
        int xv = (lane < 16) ? wsum[lane] : 0;
#pragma unroll
        for (int d = 1; d < 16; d <<= 1) {
            int u = __shfl_up_sync(0xffffffffu, xv, d);
            if (lane >= d) xv += u;
        }
        if (lane < 16) wsum[lane] = xv;
    }
    __syncthreads();
    int woff = (w > 0) ? wsum[w - 1] : 0;
    int excl = woff + sc - tot;
    if (base + 0 < N) g_incl[base + 0] = excl + v0;
    if (base + 1 < N) g_incl[base + 1] = excl + s1;
    if (base + 2 < N) g_incl[base + 2] = excl + s2;
    if (base + 3 < N) g_incl[base + 3] = excl + s3;
    if (t == 0) g_bsum[blockIdx.x] = wsum[15];
}

// ---------------- scan pass 3: inline block offset, offsets/cursors/dinv ----
__global__ void k_scan3(int N, int E) {
    int i = blockIdx.x * blockDim.x + threadIdx.x;
    if (i >= N) return;
    int blk = i / SCAN_CH;
    int boff = 0;
    for (int b = 0; b < blk; b++) boff += g_bsum[b];   // <=48 L1-broadcast loads
    int deg = g_degcnt[i];
    int off = boff + g_incl[i] - deg;
    g_off[i] = off;
    g_cur[i] = off;
    g_dinv[i] = rsqrtf((float)(deg + 1));
    if (i == 0) g_off[N] = E;
}

// ---------------- fill CSR edge list; re-zero degcnt for next call ----------
__global__ void k_fill(const int* __restrict__ src,
                       const int* __restrict__ dst, int E, int N) {
    int e = blockIdx.x * blockDim.x + threadIdx.x;
    if (e < N) g_degcnt[e] = 0;        // restore invariant for next launch
    if (e >= E) return;
    int d = dst[e];
    int s = src[e];
    int slot = atomicAdd(&g_cur[d], 1);
    g_epack[slot] = make_int2(s, __float_as_int(g_dinv[s]));
}

// ---------------- GEMM1: h1 = x @ W1  via 3xTF32 mma, double-buffered -------
#define KC 32
#define GROWS 64
#define XSTR 36
#define WSTR 24
#define NCHUNK (F_IN / KC)

__global__ __launch_bounds__(128) void k_gemm1(const float* __restrict__ x, int N) {
    __shared__ float xs[2][GROWS * XSTR];
    __shared__ float wh[2][KC * WSTR];
    __shared__ float wl[2][KC * WSTR];
    const int tid = threadIdx.x;
    const int lane = tid & 31, w = tid >> 5;
    const int row0 = blockIdx.x * GROWS;
    const int wrow = w * 16;
    const int tr = lane >> 2, tc = lane & 3;
    const int wr = tid >> 2, wq = tid & 3;

    float d[2][4] = {{0.f, 0.f, 0.f, 0.f}, {0.f, 0.f, 0.f, 0.f}};

    int lr[4], lq = tid & 7;
#pragma unroll
    for (int i = 0; i < 4; i++) {
        int idx = tid + 128 * i;
        lr[i] = idx >> 3;
    }

#pragma unroll
    for (int i = 0; i < 4; i++) {
        int gr = row0 + lr[i]; if (gr >= N) gr = N - 1;
        cp_async16(xs[0] + lr[i] * XSTR + lq * 4, x + (size_t)gr * F_IN + lq * 4);
    }
    cp_async16(wh[0] + wr * WSTR + wq * 4, g_w1hi + wr * HID + wq * 4);
    cp_async16(wl[0] + wr * WSTR + wq * 4, g_w1lo + wr * HID + wq * 4);
    cp_commit();

    for (int ch = 0; ch < NCHUNK; ch++) {
        const int b = ch & 1;
        if (ch + 1 < NCHUNK) {
            int kc = (ch + 1) * KC;
#pragma unroll
            for (int i = 0; i < 4; i++) {
                int gr = row0 + lr[i]; if (gr >= N) gr = N - 1;
                cp_async16(xs[b ^ 1] + lr[i] * XSTR + lq * 4,
                           x + (size_t)gr * F_IN + kc + lq * 4);
            }
            cp_async16(wh[b ^ 1] + wr * WSTR + wq * 4, g_w1hi + (kc + wr) * HID + wq * 4);
            cp_async16(wl[b ^ 1] + wr * WSTR + wq * 4, g_w1lo + (kc + wr) * HID + wq * 4);
            cp_commit();
            cp_wait<1>();
        } else {
            cp_wait<0>();
        }
        __syncthreads();

        const float* xb = xs[b];
        const float* whb = wh[b];
        const float* wlb = wl[b];
#pragma unroll
        for (int ks = 0; ks < KC / 8; ks++) {
            int kb = ks * 8;
            float a_f[4];
            a_f[0] = xb[(wrow + tr) * XSTR + kb + tc];
            a_f[1] = xb[(wrow + tr + 8) * XSTR + kb + tc];
            a_f[2] = xb[(wrow + tr) * XSTR + kb + tc + 4];
            a_f[3] = xb[(wrow + tr + 8) * XSTR + kb + tc + 4];
            unsigned ah[4], al[4];
#pragma unroll
            for (int j = 0; j < 4; j++) {
                ah[j] = cvt_tf32(a_f[j]);
                al[j] = cvt_tf32(a_f[j] - __uint_as_float(ah[j]));
            }
#pragma unroll
            for (int nt = 0; nt < 2; nt++) {
                int b0i = (kb + tc) * WSTR + nt * 8 + tr;
                int b1i = b0i + 4 * WSTR;
                unsigned bh0 = __float_as_uint(whb[b0i]);
                unsigned bh1 = __float_as_uint(whb[b1i]);
                unsigned bl0 = __float_as_uint(wlb[b0i]);
                unsigned bl1 = __float_as_uint(wlb[b1i]);
                mma_tf32(d[nt], ah, bh0, bh1);
                mma_tf32(d[nt], al, bh0, bh1);
                mma_tf32(d[nt], ah, bl0, bl1);
            }
        }
        __syncthreads();
    }

    int r0 = row0 + wrow + tr, r1 = r0 + 8;
#pragma unroll
    for (int nt = 0; nt < 2; nt++) {
        int c = nt * 8 + 2 * tc;
        if (r0 < N)
            *(float2*)(g_h1 + (size_t)r0 * HID + c) = make_float2(d[nt][0], d[nt][1]);
        if (r1 < N)
            *(float2*)(g_h1 + (size_t)r1 * HID + c) = make_float2(d[nt][2], d[nt][3]);
    }
}

// ---------------- gather layer 1 (warp per node) + relu + W2 -> h2 ----------
__global__ __launch_bounds__(256) void k_gather1(const float* __restrict__ b1,
                                                 const float* __restrict__ W2, int N) {
    const int warp = (blockIdx.x * blockDim.x + threadIdx.x) >> 5;
    const int lane = threadIdx.x & 31;
    if (warp >= N) return;
    const int i = warp;
    const int eg = lane >> 2, p = lane & 3;

    const int beg = g_off[i], end = g_off[i + 1];
    const float di = g_dinv[i];

    float4 acc = make_float4(0.f, 0.f, 0.f, 0.f);
#pragma unroll 4
    for (int c = beg + eg; c < end; c += 8) {
        int2 pk = g_epack[c];
        float ds = __int_as_float(pk.y);
        float4 h = *(const float4*)(g_h1 + (size_t)pk.x * HID + p * 4);
        acc.x = fmaf(ds, h.x, acc.x);
        acc.y = fmaf(ds, h.y, acc.y);
        acc.z = fmaf(ds, h.z, acc.z);
        acc.w = fmaf(ds, h.w, acc.w);
    }
#pragma unroll
    for (int d = 16; d >= 4; d >>= 1) {
        acc.x += __shfl_xor_sync(0xffffffffu, acc.x, d);
        acc.y += __shfl_xor_sync(0xffffffffu, acc.y, d);
        acc.z += __shfl_xor_sync(0xffffffffu, acc.z, d);
        acc.w += __shfl_xor_sync(0xffffffffu, acc.w, d);
    }

    float o0 = 0.f, o1 = 0.f;
    {
        float4 hs = *(const float4*)(g_h1 + (size_t)i * HID + p * 4);
        float4 bb = __ldg((const float4*)(b1 + p * 4));
        float d2 = di * di;
        float t0 = fmaxf(acc.x * di + d2 * hs.x + bb.x, 0.f);
        float t1 = fmaxf(acc.y * di + d2 * hs.y + bb.y, 0.f);
        float t2 = fmaxf(acc.z * di + d2 * hs.z + bb.z, 0.f);
        float t3 = fmaxf(acc.w * di + d2 * hs.w + bb.w, 0.f);
        int c = p * 4;
        o0 = t0 * __ldg(W2 + (c + 0) * NCLS + 0) + t1 * __ldg(W2 + (c + 1) * NCLS + 0)
           + t2 * __ldg(W2 + (c + 2) * NCLS + 0) + t3 * __ldg(W2 + (c + 3) * NCLS + 0);
        o1 = t0 * __ldg(W2 + (c + 0) * NCLS + 1) + t1 * __ldg(W2 + (c + 1) * NCLS + 1)
           + t2 * __ldg(W2 + (c + 2) * NCLS + 1) + t3 * __ldg(W2 + (c + 3) * NCLS + 1);
    }
    o0 += __shfl_xor_sync(0xffffffffu, o0, 2);
    o1 += __shfl_xor_sync(0xffffffffu, o1, 2);
    o0 += __shfl_xor_sync(0xffffffffu, o0, 1);
    o1 += __shfl_xor_sync(0xffffffffu, o1, 1);
    if (lane == 0)
        *(float2*)(g_h2 + (size_t)i * NCLS) = make_float2(o0, o1);
}

// ---------------- gather layer 2 (warp per node) + log_softmax -> out -------
__global__ __launch_bounds__(256) void k_gather2(const float* __restrict__ b2,
                                                 float* __restrict__ out, int N) {
    const int warp = (blockIdx.x * blockDim.x + threadIdx.x) >> 5;
    const int lane = threadIdx.x & 31;
    if (warp >= N) return;
    const int i = warp;
    const int beg = g_off[i], end = g_off[i + 1];
    const float di = g_dinv[i];

    float a0 = 0.f, a1 = 0.f;
#pragma unroll 4
    for (int c = beg + lane; c < end; c += 32) {
        int2 pk = g_epack[c];
        float ds = __int_as_float(pk.y);
        float2 h = *(const float2*)(g_h2 + (size_t)pk.x * NCLS);
        a0 = fmaf(ds, h.x, a0);
        a1 = fmaf(ds, h.y, a1);
    }
#pragma unroll
    for (int d = 16; d >= 1; d >>= 1) {
        a0 += __shfl_xor_sync(0xffffffffu, a0, d);
        a1 += __shfl_xor_sync(0xffffffffu, a1, d);
    }
    if (lane == 0) {
        float d2 = di * di;
        float2 hs = *(const float2*)(g_h2 + (size_t)i * NCLS);
        float v0 = a0 * di + d2 * hs.x + __ldg(b2 + 0);
        float v1 = a1 * di + d2 * hs.y + __ldg(b2 + 1);
        float m = fmaxf(v0, v1);
        float lse = m + logf(expf(v0 - m) + expf(v1 - m));
        *(float2*)(out + (size_t)i * NCLS) = make_float2(v0 - lse, v1 - lse);
    }
}

// ---------------------------------------------------------------------------
extern "C" void kernel_launch(void* const* d_in, const int* in_sizes, int n_in,
                              void* d_out, int out_size) {
    const float* x = (const float*)d_in[0];
    const int* ei = (const int*)d_in[1];
    const float* W1 = (const float*)d_in[2];
    const float* b1 = (const float*)d_in[3];
    const float* W2 = (const float*)d_in[4];
    const float* b2 = (const float*)d_in[5];
    float* out = (float*)d_out;

    const int N = in_sizes[0] / F_IN;
    const int E = in_sizes[1] / 2;
    const int* src = ei;
    const int* dst = ei + E;
    const int NB = (N + SCAN_CH - 1) / SCAN_CH;

    cudaStream_t s2;
    cudaEvent_t evFork, evJoin;
    cudaStreamCreateWithFlags(&s2, cudaStreamNonBlocking);
    cudaEventCreateWithFlags(&evFork, cudaEventDisableTiming);
    cudaEventCreateWithFlags(&evJoin, cudaEventDisableTiming);

    cudaEventRecord(evFork, 0);
    cudaStreamWaitEvent(s2, evFork, 0);

    // enqueue order => launch ids: deg0, wsplit1, scan1:2, gemm1:3 (profiled),
    // scan3:4, fill:5, gather1:6, gather2:7
    k_deg<<<(E / 4 + 255) / 256, 256>>>(dst, E);                 // main
    k_wsplit<<<(F_IN * HID + 255) / 256, 256, 0, s2>>>(W1);      // s2
    k_scan1<<<NB, 512>>>(N);                                     // main
    k_gemm1<<<(N + GROWS - 1) / GROWS, 128, 0, s2>>>(x, N);      // s2
    k_scan3<<<(N + 255) / 256, 256>>>(N, E);                     // main
    k_fill<<<(E + 511) / 512, 512>>>(src, dst, E, N);            // main
    cudaEventRecord(evJoin, s2);
    cudaStreamWaitEvent(0, evJoin, 0);
    k_gather1<<<(N * 32 + 255) / 256, 256>>>(b1, W2, N);         // main
    k_gather2<<<(N * 32 + 255) / 256, 256>>>(b2, out, N);        // main
    // stream/event objects intentionally not destroyed (must outlive capture;
    // kernel_launch runs a bounded number of times, no device memory held)
}

// round 10
// speedup vs baseline: 1.1663x; 1.1663x over previous
#include <cuda_runtime.h>
#include <cuda_bf16.h>
#include <math.h>

// ---------------------------------------------------------------------------
// 2-layer GCN via CSR-gather, forked-stream graph (R8 structure):
//   branch A (s2):  wsplit -> gemm1 (3xTF32 mma, double-buffered cp.async)
//   branch B (main): zero -> deg -> scan1 -> scan2 -> scan3 -> fill
//   join -> gather1 (agg+relu+W2) -> gather2 (agg+log_softmax)
// edge_index arrives as int32.
// ---------------------------------------------------------------------------

#define F_IN 512
#define HID  16
#define NCLS 2
#define NMAX 131072
#define EMAX 3276800
#define SCAN_CH 2048

__device__ __align__(16) int   g_degcnt[NMAX];
__device__ __align__(16) int   g_incl[NMAX];
__device__ __align__(16) int   g_off[NMAX + 1];
__device__ __align__(16) int   g_cur[NMAX];
__device__ __align__(16) int   g_bsum[256];
__device__ __align__(16) int   g_boff[256];
__device__ __align__(16) float g_dinv[NMAX];
__device__ __align__(16) float g_h1[NMAX * HID];
__device__ __align__(16) float g_h2[NMAX * NCLS];
__device__ __align__(16) int2  g_epack[EMAX];   // {src, bits(dinv[src])}
__device__ __align__(16) float g_w1hi[F_IN * HID];
__device__ __align__(16) float g_w1lo[F_IN * HID];

// ---------------- helpers ----------------
__device__ __forceinline__ unsigned cvt_tf32(float f) {
    unsigned r; asm("cvt.rna.tf32.f32 %0, %1;" : "=r"(r) : "f"(f)); return r;
}
__device__ __forceinline__ void mma_tf32(float* d, const unsigned* a,
                                         unsigned b0, unsigned b1) {
    asm("mma.sync.aligned.m16n8k8.row.col.f32.tf32.tf32.f32 "
        "{%0,%1,%2,%3}, {%4,%5,%6,%7}, {%8,%9}, {%0,%1,%2,%3};"
        : "+f"(d[0]), "+f"(d[1]), "+f"(d[2]), "+f"(d[3])
        : "r"(a[0]), "r"(a[1]), "r"(a[2]), "r"(a[3]), "r"(b0), "r"(b1));
}
__device__ __forceinline__ void cp_async16(void* smem_dst, const void* gmem_src) {
    unsigned sm;
    asm("{ .reg .u64 t; cvta.to.shared.u64 t, %1; cvt.u32.u64 %0, t; }"
        : "=r"(sm) : "l"(smem_dst));
    asm volatile("cp.async.cg.shared.global [%0], [%1], 16;"
                 :: "r"(sm), "l"(gmem_src) : "memory");
}
__device__ __forceinline__ void cp_commit() {
    asm volatile("cp.async.commit_group;" ::: "memory");
}
template <int NW>
__device__ __forceinline__ void cp_wait() {
    asm volatile("cp.async.wait_group %0;" :: "n"(NW) : "memory");
}

// ---------------- zero degree counters ----------------
__global__ void k_zero(int N) {
    int i = blockIdx.x * blockDim.x + threadIdx.x;
    if (i < N) g_degcnt[i] = 0;
}

// ---------------- degree count (4 edges / thread) ----------------
__global__ void k_deg(const int* __restrict__ dst, int E) {
    int i = blockIdx.x * blockDim.x + threadIdx.x;
    int base = i * 4;
    if (base + 3 < E) {
        int4 d = *(const int4*)(dst + base);
        atomicAdd(&g_degcnt[d.x], 1);
        atomicAdd(&g_degcnt[d.y], 1);
        atomicAdd(&g_degcnt[d.z], 1);
        atomicAdd(&g_degcnt[d.w], 1);
    } else {
        for (int e = base; e < E; e++) atomicAdd(&g_degcnt[dst[e]], 1);
    }
}

// ---------------- W1 split into tf32 hi/lo ----------------
__global__ void k_wsplit(const float* __restrict__ W1) {
    int i = blockIdx.x * blockDim.x + threadIdx.x;
    if (i >= F_IN * HID) return;
    float w = W1[i];
    unsigned hi = cvt_tf32(w);
    float hif = __uint_as_float(hi);
    g_w1hi[i] = hif;
    g_w1lo[i] = __uint_as_float(cvt_tf32(w - hif));
}

// ---------------- GEMM1: h1 = x @ W1  via 3xTF32 mma, double-buffered -------
// 256 thr = 8 warps; warp = 16 rows; block = 128 rows. KC=32 chunk staged.
#define KC 32
#define GROWS 128
#define XSTR 36
#define WSTR 24
#define NCHUNK (F_IN / KC)

__global__ __launch_bounds__(256) void k_gemm1(const float* __restrict__ x, int N) {
    __shared__ float xs[2][GROWS * XSTR];
    __shared__ float wh[2][KC * WSTR];
    __shared__ float wl[2][KC * WSTR];
    const int tid = threadIdx.x;
    const int lane = tid & 31, w = tid >> 5;
    const int row0 = blockIdx.x * GROWS;
    const int wrow = w * 16;
    const int tr = lane >> 2, tc = lane & 3;
    // W-slice loads: first 128 threads, 1 float4 each (32 rows x 4 groups)
    const int wr = (tid & 127) >> 2, wq = tid & 3;
    const bool wload = tid < 128;

    float d[2][4] = {{0.f, 0.f, 0.f, 0.f}, {0.f, 0.f, 0.f, 0.f}};

    // x tile: 128 rows x 8 float4 = 1024 slots, 256 threads -> 4 each
    int lr[4], lq = tid & 7;
#pragma unroll
    for (int i = 0; i < 4; i++) {
        int idx = tid + 256 * i;
        lr[i] = idx >> 3;
    }

    // prefetch chunk 0 -> buffer 0
#pragma unroll
    for (int i = 0; i < 4; i++) {
        int gr = row0 + lr[i]; if (gr >= N) gr = N - 1;
        cp_async16(xs[0] + lr[i] * XSTR + lq * 4, x + (size_t)gr * F_IN + lq * 4);
    }
    if (wload) {
        cp_async16(wh[0] + wr * WSTR + wq * 4, g_w1hi + wr * HID + wq * 4);
        cp_async16(wl[0] + wr * WSTR + wq * 4, g_w1lo + wr * HID + wq * 4);
    }
    cp_commit();

    for (int ch = 0; ch < NCHUNK; ch++) {
        const int b = ch & 1;
        if (ch + 1 < NCHUNK) {
            int kc = (ch + 1) * KC;
#pragma unroll
            for (int i = 0; i < 4; i++) {
                int gr = row0 + lr[i]; if (gr >= N) gr = N - 1;
                cp_async16(xs[b ^ 1] + lr[i] * XSTR + lq * 4,
                           x + (size_t)gr * F_IN + kc + lq * 4);
            }
            if (wload) {
                cp_async16(wh[b ^ 1] + wr * WSTR + wq * 4, g_w1hi + (kc + wr) * HID + wq * 4);
                cp_async16(wl[b ^ 1] + wr * WSTR + wq * 4, g_w1lo + (kc + wr) * HID + wq * 4);
            }
            cp_commit();
            cp_wait<1>();
        } else {
            cp_wait<0>();
        }
        __syncthreads();

        const float* xb = xs[b];
        const float* whb = wh[b];
        const float* wlb = wl[b];
#pragma unroll
        for (int ks = 0; ks < KC / 8; ks++) {
            int kb = ks * 8;
            float a_f[4];
            a_f[0] = xb[(wrow + tr) * XSTR + kb + tc];
            a_f[1] = xb[(wrow + tr + 8) * XSTR + kb + tc];
            a_f[2] = xb[(wrow + tr) * XSTR + kb + tc + 4];
            a_f[3] = xb[(wrow + tr + 8) * XSTR + kb + tc + 4];
            unsigned ah[4], al[4];
#pragma unroll
            for (int j = 0; j < 4; j++) {
                ah[j] = cvt_tf32(a_f[j]);
                al[j] = cvt_tf32(a_f[j] - __uint_as_float(ah[j]));
            }
#pragma unroll
            for (int nt = 0; nt < 2; nt++) {
                int b0i = (kb + tc) * WSTR + nt * 8 + tr;
                int b1i = b0i + 4 * WSTR;
                unsigned bh0 = __float_as_uint(whb[b0i]);
                unsigned bh1 = __float_as_uint(whb[b1i]);
                unsigned bl0 = __float_as_uint(wlb[b0i]);
                unsigned bl1 = __float_as_uint(wlb[b1i]);
                mma_tf32(d[nt], ah, bh0, bh1);
                mma_tf32(d[nt], al, bh0, bh1);
                mma_tf32(d[nt], ah, bl0, bl1);
            }
        }
        __syncthreads();
    }

    int r0 = row0 + wrow + tr, r1 = r0 + 8;
#pragma unroll
    for (int nt = 0; nt < 2; nt++) {
        int c = nt * 8 + 2 * tc;
        if (r0 < N)
            *(float2*)(g_h1 + (size_t)r0 * HID + c) = make_float2(d[nt][0], d[nt][1]);
        if (r1 < N)
            *(float2*)(g_h1 + (size_t)r1 * HID + c) = make_float2(d[nt][2], d[nt][3]);
    }
}

// ---------------- scan pass 1 ----------------
__global__ __launch_bounds__(512) void k_scan1(int N) {
    __shared__ int wsum[16];
    const int t = threadIdx.x;
    const int base = blockIdx.x * SCAN_CH + t * 4;
    int v0 = (base + 0 < N) ? g_degcnt[base + 0] : 0;
    int v1 = (base + 1 < N) ? g_degcnt[base + 1] : 0;
    int v2 = (base + 2 < N) ? g_degcnt[base + 2] : 0;
    int v3 = (base + 3 < N) ? g_degcnt[base + 3] : 0;
    int s1 = v0 + v1, s2 = s1 + v2, s3 = s2 + v3;
    int tot = s3;

    int lane = t & 31, w = t >> 5;
    int sc = tot;
#pragma unroll
    for (int d = 1; d < 32; d <<= 1) {
        int u = __shfl_up_sync(0xffffffffu, sc, d);
        if (lane >= d) sc += u;
    }
    if (lane == 31) wsum[w] = sc;
    __syncthreads();
    if (w == 0) {
        int xv = (lane < 16) ? wsum[lane] : 0;
#pragma unroll
        for (int d = 1; d < 16; d <<= 1) {
            int u = __shfl_up_sync(0xffffffffu, xv, d);
            if (lane >= d) xv += u;
        }
        if (lane < 16) wsum[lane] = xv;
    }
    __syncthreads();
    int woff = (w > 0) ? wsum[w - 1] : 0;
    int excl = woff + sc - tot;
    if (base + 0 < N) g_incl[base + 0] = excl + v0;
    if (base + 1 < N) g_incl[base + 1] = excl + s1;
    if (base + 2 < N) g_incl[base + 2] = excl + s2;
    if (base + 3 < N) g_incl[base + 3] = excl + s3;
    if (t == 0) g_bsum[blockIdx.x] = wsum[15];
}

// ---------------- scan pass 2: warp-scan of block sums ----------------
__global__ void k_scan2(int NB) {
    __shared__ int ws[8];
    int t = threadIdx.x;
    int lane = t & 31, w = t >> 5;
    int v = (t < NB) ? g_bsum[t] : 0;
    int s = v;
#pragma unroll
    for (int d = 1; d < 32; d <<= 1) {
        int u = __shfl_up_sync(0xffffffffu, s, d);
        if (lane >= d) s += u;
    }
    if (lane == 31) ws[w] = s;
    __syncthreads();
    if (w == 0 && lane < 8) {
        int xv = ws[lane];
#pragma unroll
        for (int d = 1; d < 8; d <<= 1) {
            int u = __shfl_up_sync(0xffu, xv, d);
            if (lane >= d) xv += u;
        }
        ws[lane] = xv;
    }
    __syncthreads();
    int off = (w > 0) ? ws[w - 1] : 0;
    if (t < NB) g_boff[t] = off + s - v;   // exclusive
}

// ---------------- scan pass 3 ----------------
__global__ void k_scan3(int N, int E) {
    int i = blockIdx.x * blockDim.x + threadIdx.x;
    if (i >= N) return;
    int deg = g_degcnt[i];
    int off = g_boff[i / SCAN_CH] + g_incl[i] - deg;
    g_off[i] = off;
    g_cur[i] = off;
    g_dinv[i] = rsqrtf((float)(deg + 1));
    if (i == 0) g_off[N] = E;
}

// ---------------- fill CSR edge list (packed src + dinv[src]) ----------------
__global__ void k_fill(const int* __restrict__ src,
                       const int* __restrict__ dst, int E) {
    int e = blockIdx.x * blockDim.x + threadIdx.x;
    if (e >= E) return;
    int d = dst[e];
    int s = src[e];
    int slot = atomicAdd(&g_cur[d], 1);
    g_epack[slot] = make_int2(s, __float_as_int(g_dinv[s]));
}

// ---------------- gather layer 1 (warp per node) + relu + W2 -> h2 ----------
__global__ __launch_bounds__(128) void k_gather1(const float* __restrict__ b1,
                                                 const float* __restrict__ W2, int N) {
    const int warp = (blockIdx.x * blockDim.x + threadIdx.x) >> 5;
    const int lane = threadIdx.x & 31;
    if (warp >= N) return;
    const int i = warp;
    const int eg = lane >> 2, p = lane & 3;

    const int beg = g_off[i], end = g_off[i + 1];
    const float di = g_dinv[i];

    float4 acc = make_float4(0.f, 0.f, 0.f, 0.f);
#pragma unroll 2
    for (int c = beg + eg; c < end; c += 8) {
        int2 pk = g_epack[c];
        float ds = __int_as_float(pk.y);
        float4 h = *(const float4*)(g_h1 + (size_t)pk.x * HID + p * 4);
        acc.x = fmaf(ds, h.x, acc.x);
        acc.y = fmaf(ds, h.y, acc.y);
        acc.z = fmaf(ds, h.z, acc.z);
        acc.w = fmaf(ds, h.w, acc.w);
    }
#pragma unroll
    for (int d = 16; d >= 4; d >>= 1) {
        acc.x += __shfl_xor_sync(0xffffffffu, acc.x, d);
        acc.y += __shfl_xor_sync(0xffffffffu, acc.y, d);
        acc.z += __shfl_xor_sync(0xffffffffu, acc.z, d);
        acc.w += __shfl_xor_sync(0xffffffffu, acc.w, d);
    }

    float o0 = 0.f, o1 = 0.f;
    {
        float4 hs = *(const float4*)(g_h1 + (size_t)i * HID + p * 4);
        float4 bb = __ldg((const float4*)(b1 + p * 4));
        float d2 = di * di;
        float t0 = fmaxf(acc.x * di + d2 * hs.x + bb.x, 0.f);
        float t1 = fmaxf(acc.y * di + d2 * hs.y + bb.y, 0.f);
        float t2 = fmaxf(acc.z * di + d2 * hs.z + bb.z, 0.f);
        float t3 = fmaxf(acc.w * di + d2 * hs.w + bb.w, 0.f);
        int c = p * 4;
        o0 = t0 * __ldg(W2 + (c + 0) * NCLS + 0) + t1 * __ldg(W2 + (c + 1) * NCLS + 0)
           + t2 * __ldg(W2 + (c + 2) * NCLS + 0) + t3 * __ldg(W2 + (c + 3) * NCLS + 0);
        o1 = t0 * __ldg(W2 + (c + 0) * NCLS + 1) + t1 * __ldg(W2 + (c + 1) * NCLS + 1)
           + t2 * __ldg(W2 + (c + 2) * NCLS + 1) + t3 * __ldg(W2 + (c + 3) * NCLS + 1);
    }
    o0 += __shfl_xor_sync(0xffffffffu, o0, 2);
    o1 += __shfl_xor_sync(0xffffffffu, o1, 2);
    o0 += __shfl_xor_sync(0xffffffffu, o0, 1);
    o1 += __shfl_xor_sync(0xffffffffu, o1, 1);
    if (lane == 0)
        *(float2*)(g_h2 + (size_t)i * NCLS) = make_float2(o0, o1);
}

// ---------------- gather layer 2 (warp per node) + log_softmax -> out -------
__global__ __launch_bounds__(128) void k_gather2(const float* __restrict__ b2,
                                                 float* __restrict__ out, int N) {
    const int warp = (blockIdx.x * blockDim.x + threadIdx.x) >> 5;
    const int lane = threadIdx.x & 31;
    if (warp >= N) return;
    const int i = warp;
    const int beg = g_off[i], end = g_off[i + 1];
    const float di = g_dinv[i];

    float a0 = 0.f, a1 = 0.f;
#pragma unroll 2
    for (int c = beg + lane; c < end; c += 32) {
        int2 pk = g_epack[c];
        float ds = __int_as_float(pk.y);
        float2 h = *(const float2*)(g_h2 + (size_t)pk.x * NCLS);
        a0 = fmaf(ds, h.x, a0);
        a1 = fmaf(ds, h.y, a1);
    }
#pragma unroll
    for (int d = 16; d >= 1; d >>= 1) {
        a0 += __shfl_xor_sync(0xffffffffu, a0, d);
        a1 += __shfl_xor_sync(0xffffffffu, a1, d);
    }
    if (lane == 0) {
        float d2 = di * di;
        float2 hs = *(const float2*)(g_h2 + (size_t)i * NCLS);
        float v0 = a0 * di + d2 * hs.x + __ldg(b2 + 0);
        float v1 = a1 * di + d2 * hs.y + __ldg(b2 + 1);
        float m = fmaxf(v0, v1);
        float lse = m + logf(expf(v0 - m) + expf(v1 - m));
        *(float2*)(out + (size_t)i * NCLS) = make_float2(v0 - lse, v1 - lse);
    }
}

// ---------------------------------------------------------------------------
extern "C" void kernel_launch(void* const* d_in, const int* in_sizes, int n_in,
                              void* d_out, int out_size) {
    const float* x = (const float*)d_in[0];
    const int* ei = (const int*)d_in[1];
    const float* W1 = (const float*)d_in[2];
    const float* b1 = (const float*)d_in[3];
    const float* W2 = (const float*)d_in[4];
    const float* b2 = (const float*)d_in[5];
    float* out = (float*)d_out;

    const int N = in_sizes[0] / F_IN;
    const int E = in_sizes[1] / 2;
    const int* src = ei;
    const int* dst = ei + E;
    const int NB = (N + SCAN_CH - 1) / SCAN_CH;

    cudaStream_t s2;
    cudaEvent_t evFork, evJoin;
    cudaStreamCreateWithFlags(&s2, cudaStreamNonBlocking);
    cudaEventCreateWithFlags(&evFork, cudaEventDisableTiming);
    cudaEventCreateWithFlags(&evJoin, cudaEventDisableTiming);

    cudaEventRecord(evFork, 0);
    cudaStreamWaitEvent(s2, evFork, 0);

    // enqueue ids: zero0, wsplit1, deg2, gemm1:3 (profiled slot), scan1:4,
    // scan2:5, scan3:6, fill:7, gather1:8, gather2:9
    k_zero<<<(N + 255) / 256, 256>>>(N);                          // main
    k_wsplit<<<(F_IN * HID + 255) / 256, 256, 0, s2>>>(W1);       // s2
    k_deg<<<(E / 4 + 255) / 256, 256>>>(dst, E);                  // main
    k_gemm1<<<(N + GROWS - 1) / GROWS, 256, 0, s2>>>(x, N);       // s2
    k_scan1<<<NB, 512>>>(N);                                      // main
    k_scan2<<<1, 256>>>(NB);                                      // main
    k_scan3<<<(N + 255) / 256, 256>>>(N, E);                      // main
    k_fill<<<(E + 511) / 512, 512>>>(src, dst, E);                // main
    cudaEventRecord(evJoin, s2);
    cudaStreamWaitEvent(0, evJoin, 0);
    k_gather1<<<(N * 32 + 127) / 128, 128>>>(b1, W2, N);          // main
    k_gather2<<<(N * 32 + 127) / 128, 128>>>(b2, out, N);         // main
    // stream/event objects intentionally not destroyed (must outlive capture)
}

// round 11
// speedup vs baseline: 1.2152x; 1.0419x over previous
#include <cuda_runtime.h>
#include <cuda_fp16.h>
#include <math.h>

// ---------------------------------------------------------------------------
// 2-layer GCN via CSR-gather, forked-stream graph:
//   k_prep (main): zero degcnt + split W1 into tf32 hi/lo
//   fork: s2: gemm1 (3xTF32 mma, double-buffered, fp16 h1 out)
//         main: deg -> scan1 -> scan3 (inline block-offset) -> fill
//   join -> gather1 (fp16 h1 agg + relu + W2) -> gather2 (+ log_softmax)
// edge_index arrives as int32.
// ---------------------------------------------------------------------------

#define F_IN 512
#define HID  16
#define NCLS 2
#define NMAX 131072
#define EMAX 3276800
#define SCAN_CH 2048

__device__ __align__(16) int    g_degcnt[NMAX];
__device__ __align__(16) int    g_incl[NMAX];
__device__ __align__(16) int    g_off[NMAX + 1];
__device__ __align__(16) int    g_cur[NMAX];
__device__ __align__(16) int    g_bsum[256];
__device__ __align__(16) float  g_dinv[NMAX];
__device__ __align__(16) __half g_h1h[NMAX * HID];   // h1 in fp16
__device__ __align__(16) float  g_h2[NMAX * NCLS];
__device__ __align__(16) int2   g_epack[EMAX];       // {src, bits(dinv[src])}
__device__ __align__(16) float  g_w1hi[F_IN * HID];
__device__ __align__(16) float  g_w1lo[F_IN * HID];

// ---------------- helpers ----------------
__device__ __forceinline__ unsigned cvt_tf32(float f) {
    unsigned r; asm("cvt.rna.tf32.f32 %0, %1;" : "=r"(r) : "f"(f)); return r;
}
__device__ __forceinline__ void mma_tf32(float* d, const unsigned* a,
                                         unsigned b0, unsigned b1) {
    asm("mma.sync.aligned.m16n8k8.row.col.f32.tf32.tf32.f32 "
        "{%0,%1,%2,%3}, {%4,%5,%6,%7}, {%8,%9}, {%0,%1,%2,%3};"
        : "+f"(d[0]), "+f"(d[1]), "+f"(d[2]), "+f"(d[3])
        : "r"(a[0]), "r"(a[1]), "r"(a[2]), "r"(a[3]), "r"(b0), "r"(b1));
}
__device__ __forceinline__ void cp_async16(void* smem_dst, const void* gmem_src) {
    unsigned sm;
    asm("{ .reg .u64 t; cvta.to.shared.u64 t, %1; cvt.u32.u64 %0, t; }"
        : "=r"(sm) : "l"(smem_dst));
    asm volatile("cp.async.cg.shared.global [%0], [%1], 16;"
                 :: "r"(sm), "l"(gmem_src) : "memory");
}
__device__ __forceinline__ void cp_commit() {
    asm volatile("cp.async.commit_group;" ::: "memory");
}
template <int NW>
__device__ __forceinline__ void cp_wait() {
    asm volatile("cp.async.wait_group %0;" :: "n"(NW) : "memory");
}

// ---------------- prep: zero degcnt + W1 tf32 split ----------------
__global__ void k_prep(const float* __restrict__ W1, int N) {
    int i = blockIdx.x * blockDim.x + threadIdx.x;
    if (i < N) g_degcnt[i] = 0;
    if (i < F_IN * HID) {
        float w = W1[i];
        unsigned hi = cvt_tf32(w);
        float hif = __uint_as_float(hi);
        g_w1hi[i] = hif;
        g_w1lo[i] = __uint_as_float(cvt_tf32(w - hif));
    }
}

// ---------------- degree count (4 edges / thread) ----------------
__global__ void k_deg(const int* __restrict__ dst, int E) {
    int i = blockIdx.x * blockDim.x + threadIdx.x;
    int base = i * 4;
    if (base + 3 < E) {
        int4 d = *(const int4*)(dst + base);
        atomicAdd(&g_degcnt[d.x], 1);
        atomicAdd(&g_degcnt[d.y], 1);
        atomicAdd(&g_degcnt[d.z], 1);
        atomicAdd(&g_degcnt[d.w], 1);
    } else {
        for (int e = base; e < E; e++) atomicAdd(&g_degcnt[dst[e]], 1);
    }
}

// ---------------- GEMM1: h1 = x @ W1 via 3xTF32 mma, double-buffered --------
#define KC 32
#define GROWS 64
#define XSTR 36
#define WSTR 24
#define NCHUNK (F_IN / KC)

__global__ __launch_bounds__(128) void k_gemm1(const float* __restrict__ x, int N) {
    __shared__ float xs[2][GROWS * XSTR];
    __shared__ float wh[2][KC * WSTR];
    __shared__ float wl[2][KC * WSTR];
    const int tid = threadIdx.x;
    const int lane = tid & 31, w = tid >> 5;
    const int row0 = blockIdx.x * GROWS;
    const int wrow = w * 16;
    const int tr = lane >> 2, tc = lane & 3;
    const int wr = tid >> 2, wq = tid & 3;

    float d[2][4] = {{0.f, 0.f, 0.f, 0.f}, {0.f, 0.f, 0.f, 0.f}};

    int lr[4], lq = tid & 7;
#pragma unroll
    for (int i = 0; i < 4; i++) {
        int idx = tid + 128 * i;
        lr[i] = idx >> 3;
    }

#pragma unroll
    for (int i = 0; i < 4; i++) {
        int gr = row0 + lr[i]; if (gr >= N) gr = N - 1;
        cp_async16(xs[0] + lr[i] * XSTR + lq * 4, x + (size_t)gr * F_IN + lq * 4);
    }
    cp_async16(wh[0] + wr * WSTR + wq * 4, g_w1hi + wr * HID + wq * 4);
    cp_async16(wl[0] + wr * WSTR + wq * 4, g_w1lo + wr * HID + wq * 4);
    cp_commit();

    for (int ch = 0; ch < NCHUNK; ch++) {
        const int b = ch & 1;
        if (ch + 1 < NCHUNK) {
            int kc = (ch + 1) * KC;
#pragma unroll
            for (int i = 0; i < 4; i++) {
                int gr = row0 + lr[i]; if (gr >= N) gr = N - 1;
                cp_async16(xs[b ^ 1] + lr[i] * XSTR + lq * 4,
                           x + (size_t)gr * F_IN + kc + lq * 4);
            }
            cp_async16(wh[b ^ 1] + wr * WSTR + wq * 4, g_w1hi + (kc + wr) * HID + wq * 4);
            cp_async16(wl[b ^ 1] + wr * WSTR + wq * 4, g_w1lo + (kc + wr) * HID + wq * 4);
            cp_commit();
            cp_wait<1>();
        } else {
            cp_wait<0>();
        }
        __syncthreads();

        const float* xb = xs[b];
        const float* whb = wh[b];
        const float* wlb = wl[b];
#pragma unroll
        for (int ks = 0; ks < KC / 8; ks++) {
            int kb = ks * 8;
            float a_f[4];
            a_f[0] = xb[(wrow + tr) * XSTR + kb + tc];
            a_f[1] = xb[(wrow + tr + 8) * XSTR + kb + tc];
            a_f[2] = xb[(wrow + tr) * XSTR + kb + tc + 4];
            a_f[3] = xb[(wrow + tr + 8) * XSTR + kb + tc + 4];
            unsigned ah[4], al[4];
#pragma unroll
            for (int j = 0; j < 4; j++) {
                ah[j] = cvt_tf32(a_f[j]);
                al[j] = cvt_tf32(a_f[j] - __uint_as_float(ah[j]));
            }
#pragma unroll
            for (int nt = 0; nt < 2; nt++) {
                int b0i = (kb + tc) * WSTR + nt * 8 + tr;
                int b1i = b0i + 4 * WSTR;
                unsigned bh0 = __float_as_uint(whb[b0i]);
                unsigned bh1 = __float_as_uint(whb[b1i]);
                unsigned bl0 = __float_as_uint(wlb[b0i]);
                unsigned bl1 = __float_as_uint(wlb[b1i]);
                mma_tf32(d[nt], ah, bh0, bh1);
                mma_tf32(d[nt], al, bh0, bh1);
                mma_tf32(d[nt], ah, bl0, bl1);
            }
        }
        __syncthreads();
    }

    int r0 = row0 + wrow + tr, r1 = r0 + 8;
#pragma unroll
    for (int nt = 0; nt < 2; nt++) {
        int c = nt * 8 + 2 * tc;
        if (r0 < N)
            *(__half2*)(g_h1h + (size_t)r0 * HID + c) =
                __floats2half2_rn(d[nt][0], d[nt][1]);
        if (r1 < N)
            *(__half2*)(g_h1h + (size_t)r1 * HID + c) =
                __floats2half2_rn(d[nt][2], d[nt][3]);
    }
}

// ---------------- scan pass 1: per-block inclusive scan + block sums --------
__global__ __launch_bounds__(512) void k_scan1(int N) {
    __shared__ int wsum[16];
    const int t = threadIdx.x;
    const int base = blockIdx.x * SCAN_CH + t * 4;
    int v0 = (base + 0 < N) ? g_degcnt[base + 0] : 0;
    int v1 = (base + 1 < N) ? g_degcnt[base + 1] : 0;
    int v2 = (base + 2 < N) ? g_degcnt[base + 2] : 0;
    int v3 = (base + 3 < N) ? g_degcnt[base + 3] : 0;
    int s1 = v0 + v1, s2 = s1 + v2, s3 = s2 + v3;
    int tot = s3;

    int lane = t & 31, w = t >> 5;
    int sc = tot;
#pragma unroll
    for (int d = 1; d < 32; d <<= 1) {
        int u = __shfl_up_sync(0xffffffffu, sc, d);
        if (lane >= d) sc += u;
    }
    if (lane == 31) wsum[w] = sc;
    __syncthreads();
    if (w == 0) {
        int xv = (lane < 16) ? wsum[lane] : 0;
#pragma unroll
        for (int d = 1; d < 16; d <<= 1) {
            int u = __shfl_up_sync(0xffffffffu, xv, d);
            if (lane >= d) xv += u;
        }
        if (lane < 16) wsum[lane] = xv;
    }
    __syncthreads();
    int woff = (w > 0) ? wsum[w - 1] : 0;
    int excl = woff + sc - tot;
    if (base + 0 < N) g_incl[base + 0] = excl + v0;
    if (base + 1 < N) g_incl[base + 1] = excl + s1;
    if (base + 2 < N) g_incl[base + 2] = excl + s2;
    if (base + 3 < N) g_incl[base + 3] = excl + s3;
    if (t == 0) g_bsum[blockIdx.x] = wsum[15];
}

// ---------------- scan pass 3: inline block offset; offsets/cursors/dinv ----
__global__ void k_scan3(int N, int E) {
    int i = blockIdx.x * blockDim.x + threadIdx.x;
    if (i >= N) return;
    int blk = i / SCAN_CH;
    int boff = 0;
    for (int b = 0; b < blk; b++) boff += g_bsum[b];   // uniform, L1-broadcast
    int deg = g_degcnt[i];
    int off = boff + g_incl[i] - deg;
    g_off[i] = off;
    g_cur[i] = off;
    g_dinv[i] = rsqrtf((float)(deg + 1));
    if (i == 0) g_off[N] = E;
}

// ---------------- fill CSR edge list (packed src + dinv[src]) ----------------
__global__ void k_fill(const int* __restrict__ src,
                       const int* __restrict__ dst, int E) {
    int e = blockIdx.x * blockDim.x + threadIdx.x;
    if (e >= E) return;
    int d = dst[e];
    int s = src[e];
    int slot = atomicAdd(&g_cur[d], 1);
    g_epack[slot] = make_int2(s, __float_as_int(g_dinv[s]));
}

// ---------------- gather layer 1 (warp per node, fp16 h1) -------------------
__global__ __launch_bounds__(128) void k_gather1(const float* __restrict__ b1,
                                                 const float* __restrict__ W2, int N) {
    const int warp = (blockIdx.x * blockDim.x + threadIdx.x) >> 5;
    const int lane = threadIdx.x & 31;
    if (warp >= N) return;
    const int i = warp;
    const int eg = lane >> 2, p = lane & 3;

    const int beg = g_off[i], end = g_off[i + 1];
    const float di = g_dinv[i];

    float4 acc = make_float4(0.f, 0.f, 0.f, 0.f);
#pragma unroll 2
    for (int c = beg + eg; c < end; c += 8) {
        int2 pk = g_epack[c];
        float ds = __int_as_float(pk.y);
        uint2 hv = *(const uint2*)(g_h1h + (size_t)pk.x * HID + p * 4);
        float2 f0 = __half22float2(*(__half2*)&hv.x);
        float2 f1 = __half22float2(*(__half2*)&hv.y);
        acc.x = fmaf(ds, f0.x, acc.x);
        acc.y = fmaf(ds, f0.y, acc.y);
        acc.z = fmaf(ds, f1.x, acc.z);
        acc.w = fmaf(ds, f1.y, acc.w);
    }
#pragma unroll
    for (int d = 16; d >= 4; d >>= 1) {
        acc.x += __shfl_xor_sync(0xffffffffu, acc.x, d);
        acc.y += __shfl_xor_sync(0xffffffffu, acc.y, d);
        acc.z += __shfl_xor_sync(0xffffffffu, acc.z, d);
        acc.w += __shfl_xor_sync(0xffffffffu, acc.w, d);
    }

    float o0 = 0.f, o1 = 0.f;
    {
        uint2 hv = *(const uint2*)(g_h1h + (size_t)i * HID + p * 4);
        float2 h0 = __half22float2(*(__half2*)&hv.x);
        float2 h1 = __half22float2(*(__half2*)&hv.y);
        float4 bb = __ldg((const float4*)(b1 + p * 4));
        float d2 = di * di;
        float t0 = fmaxf(acc.x * di + d2 * h0.x + bb.x, 0.f);
        float t1 = fmaxf(acc.y * di + d2 * h0.y + bb.y, 0.f);
        float t2 = fmaxf(acc.z * di + d2 * h1.x + bb.z, 0.f);
        float t3 = fmaxf(acc.w * di + d2 * h1.y + bb.w, 0.f);
        int c = p * 4;
        o0 = t0 * __ldg(W2 + (c + 0) * NCLS + 0) + t1 * __ldg(W2 + (c + 1) * NCLS + 0)
           + t2 * __ldg(W2 + (c + 2) * NCLS + 0) + t3 * __ldg(W2 + (c + 3) * NCLS + 0);
        o1 = t0 * __ldg(W2 + (c + 0) * NCLS + 1) + t1 * __ldg(W2 + (c + 1) * NCLS + 1)
           + t2 * __ldg(W2 + (c + 2) * NCLS + 1) + t3 * __ldg(W2 + (c + 3) * NCLS + 1);
    }
    o0 += __shfl_xor_sync(0xffffffffu, o0, 2);
    o1 += __shfl_xor_sync(0xffffffffu, o1, 2);
    o0 += __shfl_xor_sync(0xffffffffu, o0, 1);
    o1 += __shfl_xor_sync(0xffffffffu, o1, 1);
    if (lane == 0)
        *(float2*)(g_h2 + (size_t)i * NCLS) = make_float2(o0, o1);
}

// ---------------- gather layer 2 (warp per node) + log_softmax -> out -------
__global__ __launch_bounds__(128) void k_gather2(const float* __restrict__ b2,
                                                 float* __restrict__ out, int N) {
    const int warp = (blockIdx.x * blockDim.x + threadIdx.x) >> 5;
    const int lane = threadIdx.x & 31;
    if (warp >= N) return;
    const int i = warp;
    const int beg = g_off[i], end = g_off[i + 1];
    const float di = g_dinv[i];

    float a0 = 0.f, a1 = 0.f;
#pragma unroll 2
    for (int c = beg + lane; c < end; c += 32) {
        int2 pk = g_epack[c];
        float ds = __int_as_float(pk.y);
        float2 h = *(const float2*)(g_h2 + (size_t)pk.x * NCLS);
        a0 = fmaf(ds, h.x, a0);
        a1 = fmaf(ds, h.y, a1);
    }
#pragma unroll
    for (int d = 16; d >= 1; d >>= 1) {
        a0 += __shfl_xor_sync(0xffffffffu, a0, d);
        a1 += __shfl_xor_sync(0xffffffffu, a1, d);
    }
    if (lane == 0) {
        float d2 = di * di;
        float2 hs = *(const float2*)(g_h2 + (size_t)i * NCLS);
        float v0 = a0 * di + d2 * hs.x + __ldg(b2 + 0);
        float v1 = a1 * di + d2 * hs.y + __ldg(b2 + 1);
        float m = fmaxf(v0, v1);
        float lse = m + logf(expf(v0 - m) + expf(v1 - m));
        *(float2*)(out + (size_t)i * NCLS) = make_float2(v0 - lse, v1 - lse);
    }
}

// ---------------------------------------------------------------------------
extern "C" void kernel_launch(void* const* d_in, const int* in_sizes, int n_in,
                              void* d_out, int out_size) {
    const float* x = (const float*)d_in[0];
    const int* ei = (const int*)d_in[1];
    const float* W1 = (const float*)d_in[2];
    const float* b1 = (const float*)d_in[3];
    const float* W2 = (const float*)d_in[4];
    const float* b2 = (const float*)d_in[5];
    float* out = (float*)d_out;

    const int N = in_sizes[0] / F_IN;
    const int E = in_sizes[1] / 2;
    const int* src = ei;
    const int* dst = ei + E;
    const int NB = (N + SCAN_CH - 1) / SCAN_CH;

    cudaStream_t s2;
    cudaEvent_t evFork, evJoin;
    cudaStreamCreateWithFlags(&s2, cudaStreamNonBlocking);
    cudaEventCreateWithFlags(&evFork, cudaEventDisableTiming);
    cudaEventCreateWithFlags(&evJoin, cudaEventDisableTiming);

    // prep on main, then fork
    k_prep<<<(N + 255) / 256, 256>>>(W1, N);
    cudaEventRecord(evFork, 0);
    cudaStreamWaitEvent(s2, evFork, 0);

    // branch A (s2): GEMM
    k_gemm1<<<(N + GROWS - 1) / GROWS, 128, 0, s2>>>(x, N);
    cudaEventRecord(evJoin, s2);

    // branch B (main): CSR build
    k_deg<<<(E / 4 + 255) / 256, 256>>>(dst, E);
    k_scan1<<<NB, 512>>>(N);
    k_scan3<<<(N + 255) / 256, 256>>>(N, E);
    k_fill<<<(E + 511) / 512, 512>>>(src, dst, E);

    // join, then gathers
    cudaStreamWaitEvent(0, evJoin, 0);
    k_gather1<<<(N * 32 + 127) / 128, 128>>>(b1, W2, N);
    k_gather2<<<(N * 32 + 127) / 128, 128>>>(b2, out, N);
    // stream/event objects intentionally not destroyed (must outlive capture)
}